// round 15
// baseline (speedup 1.0000x reference)
#include <cuda_runtime.h>
#include <cuda_fp16.h>
#include <cstdint>

// Problem constants (fixed by the reference)
#define B_    2
#define T_    512
#define D_    768
#define E_    256
#define P_    65536
#define H1_   768
#define H2_   384
#define NL_   5
#define ROWS_ (B_*E_)          // 512 fused (b,e) rows

#define PL1_SLAB (ROWS_*H1_)   // 393216
#define PL2_SLAB (ROWS_*H2_)   // 196608
#define PU_SLAB  (ROWS_*2*H2_) // 393216

// ---------------- scratch (static device globals; no allocation) ------------
__device__ float g_eph[NL_*H1_];            // emb @ Wh1[768:]         [5,768]
__device__ float g_ept[NL_*H1_];            // emb @ Wt1[768:]         [5,768]
__device__ float g_Pl1[8*PL1_SLAB];         // L1 partials [net*4+kp]
__device__ float g_Pl2[16*PL2_SLAB];        // L2 partials [net*8+kp]
__device__ float g_head[ROWS_*H2_];         // head_all fp32 (lhlt)
__device__ float g_tail[ROWS_*H2_];         // tail_all fp32 (lhlt)
__device__ float g_Pu[6*PU_SLAB];           // u partials [kp]
__device__ float g_Vp[16*E_*E_];            // V partials [bo*4+kp][256*256]
__device__ float g_lh[ROWS_*2];
__device__ float g_lt[ROWS_*2];

// packed hi/lo half2 planes (u32 = half2 of one k-pair), all 16B aligned
__device__ __align__(16) uint32_t g_pooledP_h[512*384], g_pooledP_l[512*384];
__device__ __align__(16) uint32_t g_W1P_h[2*768*384],  g_W1P_l[2*768*384];
__device__ __align__(16) uint32_t g_W2P_h[2*384*384],  g_W2P_l[2*384*384];
__device__ __align__(16) uint32_t g_WbilP_h[768*192],  g_WbilP_l[768*192];
__device__ __align__(16) uint32_t g_h1P_h[2*512*384],  g_h1P_l[2*512*384];
__device__ __align__(16) uint32_t g_headP_h[512*192],  g_headP_l[512*192];
__device__ __align__(16) uint32_t g_tailP_h[512*192],  g_tailP_l[512*192];
__device__ __align__(16) uint32_t g_UP_h[512*384],     g_UP_l[512*384];

// ---------------- fp16 helpers ----------------------------------------------
__device__ __forceinline__ void mma_f16(float c[4],
                                        const uint32_t a[4],
                                        const uint32_t b[2]) {
    asm volatile(
        "mma.sync.aligned.m16n8k16.row.col.f32.f16.f16.f32 "
        "{%0,%1,%2,%3}, {%4,%5,%6,%7}, {%8,%9}, {%0,%1,%2,%3};"
        : "+f"(c[0]), "+f"(c[1]), "+f"(c[2]), "+f"(c[3])
        : "r"(a[0]), "r"(a[1]), "r"(a[2]), "r"(a[3]), "r"(b[0]), "r"(b[1]));
}
__device__ __forceinline__ uint32_t pk2(__half a, __half b) {
    __half2 t = __halves2half2(a, b);
    return *reinterpret_cast<uint32_t*>(&t);
}
__device__ __forceinline__ void hsplit2(float x0, float x1,
                                        uint32_t& hi, uint32_t& lo) {
    __half h0 = __float2half_rn(x0), h1 = __float2half_rn(x1);
    float l0 = x0 - __half2float(h0);
    float l1 = x1 - __half2float(h1);
    hi = pk2(h0, h1);
    lo = pk2(__float2half_rn(l0), __float2half_rn(l1));
}

// ---------------- cp.async helpers ------------------------------------------
__device__ __forceinline__ uint32_t smem_u32(const void* p) {
    return (uint32_t)__cvta_generic_to_shared(p);
}
__device__ __forceinline__ void cp16(uint32_t dst, const void* src) {
    asm volatile("cp.async.cg.shared.global [%0], [%1], 16;"
                 :: "r"(dst), "l"(src) : "memory");
}
__device__ __forceinline__ void cp_commit() {
    asm volatile("cp.async.commit_group;" ::: "memory");
}
template<int NN> __device__ __forceinline__ void cp_wait() {
    asm volatile("cp.async.wait_group %0;" :: "n"(NN) : "memory");
}

// smem layout (validated): u32 words, stride 36 per row.
// Row: words 0..15 = hi k-pairs 0..15, 16..31 = lo.  A 128 rows, B 64 rows.
#define AW2      36
#define A_BUF_W  (128*AW2)   // 4608
#define B_BUF_W  (64*AW2)    // 2304
#define SM_WORDS (2*A_BUF_W + 2*B_BUF_W)  // 13824 words = 55296 B
#define SM_BYTES (SM_WORDS*4)

// ---------------- packed-operand GEMM core (BK=32, cp.async staging) --------
// C[bm:bm+128, bn:bn+64] = 3-term fp16-split product of packed A,B (NT).
// A planes [M][ldaW] (ldaW = total kpairs), B planes [N][ldbW].
// kpStart in kpairs (multiple of 4), nk = number of 16-kpair tiles.
__device__ __forceinline__ void gemm_core_p(
    const uint32_t* __restrict__ Ahi, const uint32_t* __restrict__ Alo, int ldaW,
    const uint32_t* __restrict__ Bhi, const uint32_t* __restrict__ Blo, int ldbW,
    float* __restrict__ C, int N, int kpStart, int nk)
{
    extern __shared__ uint32_t smw[];
    uint32_t* As = smw;                 // 2 bufs x A_BUF_W
    uint32_t* Bs = smw + 2*A_BUF_W;     // 2 bufs x B_BUF_W

    const int tid = threadIdx.x;
    const int bm = blockIdx.y * 128, bn = blockIdx.x * 64;
    const int lane = tid & 31, wid = tid >> 5;
    const int wm = wid & 3, wn = wid >> 2;     // 4 x 2 warp grid
    const int q = lane >> 2, r = lane & 3;

    // A staging: row = tid>>1, half = tid&1 (8 hi + 8 lo words each)
    const int arow = tid >> 1, ahalf = tid & 1;
    const uint32_t* gAh = Ahi + (size_t)(bm+arow)*ldaW + kpStart + ahalf*8;
    const uint32_t* gAl = Alo + (size_t)(bm+arow)*ldaW + kpStart + ahalf*8;
    const uint32_t sA = smem_u32(As) + (uint32_t)(arow*AW2 + ahalf*8)*4;

    // B staging: row = tid>>2, quarter = tid&3 (4 hi + 4 lo words each)
    const int brow = tid >> 2, bq = tid & 3;
    const uint32_t* gBh = Bhi + (size_t)(bn+brow)*ldbW + kpStart + bq*4;
    const uint32_t* gBl = Blo + (size_t)(bn+brow)*ldbW + kpStart + bq*4;
    const uint32_t sB = smem_u32(Bs) + (uint32_t)(brow*AW2 + bq*4)*4;

    auto issue = [&](int t, int buf) {
        uint32_t a = sA + (uint32_t)buf*(A_BUF_W*4);
        const uint32_t* sh = gAh + t*16;
        const uint32_t* sl = gAl + t*16;
        cp16(a,      sh);     cp16(a + 16, sh + 4);
        cp16(a + 64, sl);     cp16(a + 80, sl + 4);
        uint32_t b = sB + (uint32_t)buf*(B_BUF_W*4);
        cp16(b,      gBh + t*16);
        cp16(b + 64, gBl + t*16);
        cp_commit();
    };

    float acc[2][4][4];
    #pragma unroll
    for (int f = 0; f < 2; f++)
        #pragma unroll
        for (int g = 0; g < 4; g++)
            #pragma unroll
            for (int i = 0; i < 4; i++) acc[f][g][i] = 0.f;

    issue(0, 0);
    if (nk > 1) issue(1, 1);

    for (int t = 0; t < nk; t++) {
        int cur = t & 1;
        if (t + 1 < nk) cp_wait<1>(); else cp_wait<0>();
        __syncthreads();

        // ---- compute tile t from buffer cur (validated core) ----
        #pragma unroll
        for (int s = 0; s < 2; s++) {
            uint32_t ah[2][4], al[2][4];
            #pragma unroll
            for (int f = 0; f < 2; f++) {
                int m0 = wm*32 + f*16 + q;
                int w0 = cur*A_BUF_W + m0*AW2 + s*8 + r;
                int w1 = cur*A_BUF_W + (m0+8)*AW2 + s*8 + r;
                ah[f][0] = As[w0];      ah[f][1] = As[w1];
                ah[f][2] = As[w0+4];    ah[f][3] = As[w1+4];
                al[f][0] = As[w0+16];   al[f][1] = As[w1+16];
                al[f][2] = As[w0+20];   al[f][3] = As[w1+20];
            }
            #pragma unroll
            for (int g = 0; g < 4; g++) {
                int nn = wn*32 + g*8 + q;
                int wb = cur*B_BUF_W + nn*AW2 + s*8 + r;
                uint32_t bh[2] = {Bs[wb],    Bs[wb+4]};
                uint32_t bl[2] = {Bs[wb+16], Bs[wb+20]};
                #pragma unroll
                for (int f = 0; f < 2; f++) {
                    mma_f16(acc[f][g], ah[f], bh);
                    mma_f16(acc[f][g], ah[f], bl);
                    mma_f16(acc[f][g], al[f], bh);
                }
            }
        }
        __syncthreads();                       // all reads of buf cur done
        if (t + 2 < nk) issue(t + 2, cur);     // refill cur for tile t+2
    }

    // epilogue: m16n8 frag: c0 (q,2r), c1 (q,2r+1), c2 (q+8,2r), c3 (q+8,2r+1)
    #pragma unroll
    for (int f = 0; f < 2; f++) {
        int row0 = bm + wm*32 + f*16 + q;
        #pragma unroll
        for (int g = 0; g < 4; g++) {
            int ncol = bn + wn*32 + g*8 + r*2;
            *(float2*)(C + (size_t)row0*N + ncol) =
                make_float2(acc[f][g][0], acc[f][g][1]);
            *(float2*)(C + (size_t)(row0+8)*N + ncol) =
                make_float2(acc[f][g][2], acc[f][g][3]);
        }
    }
}

// ---------------- GEMM wrappers (3 blocks/SM, deeper split-K) ----------------
// L1: Pl1[net*4+kp] = pooled @ W1[net] slice   grid(12,4,8) = 384
__global__ __launch_bounds__(256, 3) void k_l1(float* __restrict__ Pl1)
{
    int z = blockIdx.z, net = z >> 2, kp = z & 3;
    gemm_core_p(g_pooledP_h, g_pooledP_l, 384,
                g_W1P_h + (size_t)net*768*384, g_W1P_l + (size_t)net*768*384, 384,
                Pl1 + (size_t)z*PL1_SLAB, H1_, kp*96, 6);
}

// L2: Pl2[net*8+kp] = h1[net] @ W2[net]   grid(6,4,16) = 384
__global__ __launch_bounds__(256, 3) void k_l2(float* __restrict__ Pl2)
{
    int z = blockIdx.z, net = z >> 3, kp = z & 7;
    gemm_core_p(g_h1P_h + (size_t)net*512*384, g_h1P_l + (size_t)net*512*384, 384,
                g_W2P_h + (size_t)net*384*384, g_W2P_l + (size_t)net*384*384, 384,
                Pl2 + (size_t)z*PL2_SLAB, H2_, kp*48, 3);
}

// u: Pu[kp] = head @ W_bil   grid(12,4,6) = 288
__global__ __launch_bounds__(256, 3) void k_u(float* __restrict__ Pu)
{
    int kp = blockIdx.z;
    gemm_core_p(g_headP_h, g_headP_l, 192,
                g_WbilP_h, g_WbilP_l, 192,
                Pu + (size_t)kp*PU_SLAB, 2*H2_, kp*32, 2);
}

// V: Vp[bo*4+kp] = U[b,:,o-slice] @ tail_b^T   grid(4,2,16) = 128
__global__ __launch_bounds__(256, 3) void k_V(float* __restrict__ Vp)
{
    int z = blockIdx.z, bo = z >> 2, kp = z & 3;
    int b = bo >> 1, o = bo & 1;
    gemm_core_p(g_UP_h + (size_t)(b*E_)*384 + o*192,
                g_UP_l + (size_t)(b*E_)*384 + o*192, 384,
                g_tailP_h + (size_t)(b*E_)*192,
                g_tailP_l + (size_t)(b*E_)*192, 192,
                Vp + (size_t)z*E_*E_, E_, kp*48, 3);
}

// ---------------- merged prep: pool-pack + labelproj + weight-pack -----------
#define PREP_POOL   512
#define PREP_LPROJ  (PREP_POOL + 30)
#define PREP_TOTAL  (PREP_LPROJ + 1008)

__global__ void prep_kernel(const float* __restrict__ hs,
                            const int* __restrict__ st,
                            const int* __restrict__ en,
                            const float* __restrict__ emb,
                            const float* __restrict__ Wh1,
                            const float* __restrict__ Wt1,
                            const float* __restrict__ Wh2,
                            const float* __restrict__ Wt2,
                            const float* __restrict__ Wbil) {
    __shared__ float sbuf[64][33];
    int bz = blockIdx.x;
    int tid = threadIdx.x;

    if (bz < PREP_POOL) {
        int be = bz;
        int b  = be >> 8;
        int s  = st[be];
        int len = en[be] - s;
        int cl  = len < 1 ? 1 : len;
        float inv = 1.0f / (float)cl;
        const float* base = hs + ((size_t)(b*T_ + s))*D_;
        for (int dp = tid; dp < D_/2; dp += blockDim.x) {
            int d = 2*dp;
            float a0 = 0.f, a1 = 0.f;
            for (int t = 0; t < len; t++) {
                a0 += base[(size_t)t*D_ + d];
                a1 += base[(size_t)t*D_ + d + 1];
            }
            uint32_t hi, lo;
            hsplit2(a0*inv, a1*inv, hi, lo);
            g_pooledP_h[(size_t)be*384 + dp] = hi;
            g_pooledP_l[(size_t)be*384 + dp] = lo;
        }
        return;
    }
    if (bz < PREP_LPROJ) {
        int gid = (bz - PREP_POOL)*256 + tid;      // < 7680 = 2*NL*H1
        int half = gid / (NL_*H1_);
        int rr   = gid - half*(NL_*H1_);
        int l = rr / H1_, n = rr - l*H1_;
        const float* W1 = half ? Wt1 : Wh1;
        const float* wp = W1 + (size_t)D_*H1_ + n;
        const float* ep = emb + (size_t)l*D_;
        float acc = 0.f;
        #pragma unroll 4
        for (int k = 0; k < D_; k++) acc += ep[k] * wp[(size_t)k*H1_];
        if (half) g_ept[rr] = acc; else g_eph[rr] = acc;
        return;
    }

    int job = bz - PREP_LPROJ;
    const float* src; int K, N; uint32_t *dh, *dl; int local;
    if (job < 288)      { src = Wh1;            K=768; N=768; dh=g_W1P_h;             dl=g_W1P_l;             local=job; }
    else if (job < 576) { src = Wt1;            K=768; N=768; dh=g_W1P_h+768*384;     dl=g_W1P_l+768*384;     local=job-288; }
    else if (job < 720) { src = Wh2;            K=768; N=384; dh=g_W2P_h;             dl=g_W2P_l;             local=job-576; }
    else if (job < 864) { src = Wt2;            K=768; N=384; dh=g_W2P_h+384*384;     dl=g_W2P_l+384*384;     local=job-720; }
    else if (job < 936) { src = Wbil;           K=384; N=384; dh=g_WbilP_h;           dl=g_WbilP_l;           local=job-864; }
    else                { src = Wbil+384*384;   K=384; N=384; dh=g_WbilP_h+384*192;   dl=g_WbilP_l+384*192;   local=job-936; }
    int ntiles = N >> 5;
    int kt = local / ntiles, nt = local - kt*ntiles;

    for (int i = tid; i < 64*32; i += 256) {
        int kk = i >> 5, n = i & 31;
        sbuf[kk][n] = src[(size_t)(kt*64 + kk)*N + nt*32 + n];
    }
    __syncthreads();
    int ldW = K >> 1;
    for (int i = tid; i < 32*32; i += 256) {
        int n = i >> 5, p = i & 31;
        uint32_t hi, lo;
        hsplit2(sbuf[2*p][n], sbuf[2*p+1][n], hi, lo);
        size_t off = (size_t)(nt*32 + n)*ldW + kt*32 + p;
        dh[off] = hi;
        dl[off] = lo;
    }
}

// ---------------- combine L1: h1P = pack(relu(sum4 Pl1 + b1 + lbias)) -------
__global__ void combine_l1(const float* __restrict__ bh1,
                           const float* __restrict__ bt1,
                           const int* __restrict__ labels) {
    int gid = blockIdx.x*blockDim.x + threadIdx.x;   // 2*512*384
    if (gid >= 2*512*384) return;
    int net = gid / (512*384);
    int rr  = gid - net*(512*384);
    int row = rr / 384, wp = rr - row*384;
    int col = 2*wp;
    const float* bs = net ? bt1 : bh1;
    const float* lb = (net ? g_ept : g_eph) + (size_t)labels[row]*H1_ + col;
    float v0 = bs[col]   + lb[0];
    float v1 = bs[col+1] + lb[1];
    #pragma unroll
    for (int kp = 0; kp < 4; kp++) {
        const float* p = g_Pl1 + (size_t)(net*4+kp)*PL1_SLAB + (size_t)row*H1_ + col;
        v0 += p[0]; v1 += p[1];
    }
    v0 = fmaxf(v0, 0.f); v1 = fmaxf(v1, 0.f);
    uint32_t hi, lo;
    hsplit2(v0, v1, hi, lo);
    g_h1P_h[(size_t)net*512*384 + rr] = hi;
    g_h1P_l[(size_t)net*512*384 + rr] = lo;
}

// ---------------- combine L2: head/tail fp32 + packed ------------------------
__global__ void combine_l2(const float* __restrict__ bh2,
                           const float* __restrict__ bt2) {
    int gid = blockIdx.x*blockDim.x + threadIdx.x;   // 2*512*192
    if (gid >= 2*512*192) return;
    int net = gid / (512*192);
    int rr  = gid - net*(512*192);
    int row = rr / 192, wp = rr - row*192;
    int col = 2*wp;
    const float* bs = net ? bt2 : bh2;
    float v0 = bs[col], v1 = bs[col+1];
    #pragma unroll
    for (int kp = 0; kp < 8; kp++) {
        const float* p = g_Pl2 + (size_t)(net*8+kp)*PL2_SLAB + (size_t)row*H2_ + col;
        v0 += p[0]; v1 += p[1];
    }
    v0 = fmaxf(v0, 0.f); v1 = fmaxf(v1, 0.f);
    uint32_t hi, lo;
    hsplit2(v0, v1, hi, lo);
    if (net) {
        g_tail[(size_t)row*H2_ + col] = v0;
        g_tail[(size_t)row*H2_ + col + 1] = v1;
        g_tailP_h[rr] = hi; g_tailP_l[rr] = lo;
    } else {
        g_head[(size_t)row*H2_ + col] = v0;
        g_head[(size_t)row*H2_ + col + 1] = v1;
        g_headP_h[rr] = hi; g_headP_l[rr] = lo;
    }
}

// ---------------- combine u: UP = pack(sum6 Pu) ------------------------------
__global__ void combine_u() {
    int gid = blockIdx.x*blockDim.x + threadIdx.x;   // 512*384
    if (gid >= 512*384) return;
    int row = gid / 384, wp = gid - row*384;
    int col = 2*wp;
    float v0 = 0.f, v1 = 0.f;
    #pragma unroll
    for (int kp = 0; kp < 6; kp++) {
        const float* p = g_Pu + (size_t)kp*PU_SLAB + (size_t)row*(2*H2_) + col;
        v0 += p[0]; v1 += p[1];
    }
    uint32_t hi, lo;
    hsplit2(v0, v1, hi, lo);
    g_UP_h[gid] = hi;
    g_UP_l[gid] = lo;
}

// ---------------- per-entity linear terms lh/lt -----------------------------
__global__ void lhlt_kernel(const float* __restrict__ Wlin) {
    int gid  = blockIdx.x*blockDim.x + threadIdx.x;
    int w    = gid >> 5;
    int lane = gid & 31;
    if (w >= ROWS_) return;
    float s0=0.f, s1=0.f, s2=0.f, s3=0.f;
    for (int j = lane; j < H2_; j += 32) {
        float hv = g_head[(size_t)w*H2_ + j];
        float tv = g_tail[(size_t)w*H2_ + j];
        s0 += hv * Wlin[j*2+0];
        s1 += hv * Wlin[j*2+1];
        s2 += tv * Wlin[(H2_+j)*2+0];
        s3 += tv * Wlin[(H2_+j)*2+1];
    }
    #pragma unroll
    for (int off = 16; off > 0; off >>= 1) {
        s0 += __shfl_down_sync(0xffffffffu, s0, off);
        s1 += __shfl_down_sync(0xffffffffu, s1, off);
        s2 += __shfl_down_sync(0xffffffffu, s2, off);
        s3 += __shfl_down_sync(0xffffffffu, s3, off);
    }
    if (lane == 0) {
        g_lh[w*2+0] = s0; g_lh[w*2+1] = s1;
        g_lt[w*2+0] = s2; g_lt[w*2+1] = s3;
    }
}

// ---------------- final per-pair lookup (sums 4 V partials per o) -----------
__global__ void gather_kernel(const int* __restrict__ hidx,
                              const int* __restrict__ tidx,
                              const float* __restrict__ blin,
                              float* __restrict__ out) {
    int gid = blockIdx.x*blockDim.x + threadIdx.x;   // B*P = 131072
    if (gid >= B_*P_) return;
    int b = gid >> 16;
    int h = hidx[gid];
    int t = tidx[gid];
    int rh = (b << 8) + h;
    int rt = (b << 8) + t;
    size_t off = (size_t)(h << 8) + t;
    float v0 = 0.f, v1 = 0.f;
    #pragma unroll
    for (int kp = 0; kp < 4; kp++) {
        v0 += g_Vp[(((size_t)(b*2+0)*4 + kp) << 16) + off];
        v1 += g_Vp[(((size_t)(b*2+1)*4 + kp) << 16) + off];
    }
    float2 r;
    r.x = v0 + g_lh[rh*2+0] + g_lt[rt*2+0] + blin[0];
    r.y = v1 + g_lh[rh*2+1] + g_lt[rt*2+1] + blin[1];
    ((float2*)out)[gid] = r;
}

// ---------------- launch ----------------------------------------------------
extern "C" void kernel_launch(void* const* d_in, const int* in_sizes, int n_in,
                              void* d_out, int out_size) {
    const float* hs   = (const float*)d_in[0];
    const float* emb  = (const float*)d_in[1];
    const float* Wh1  = (const float*)d_in[2];
    const float* bh1  = (const float*)d_in[3];
    const float* Wh2  = (const float*)d_in[4];
    const float* bh2  = (const float*)d_in[5];
    const float* Wt1  = (const float*)d_in[6];
    const float* bt1  = (const float*)d_in[7];
    const float* Wt2  = (const float*)d_in[8];
    const float* bt2  = (const float*)d_in[9];
    const float* Wbil = (const float*)d_in[10];
    const float* Wlin = (const float*)d_in[11];
    const float* blin = (const float*)d_in[12];
    const int*   est  = (const int*)d_in[13];
    const int*   een  = (const int*)d_in[14];
    const int*   elab = (const int*)d_in[15];
    const int*   hidx = (const int*)d_in[16];
    const int*   tidx = (const int*)d_in[17];

    float *p_Pl1, *p_Pl2, *p_Pu, *p_Vp;
    cudaGetSymbolAddress((void**)&p_Pl1, g_Pl1);
    cudaGetSymbolAddress((void**)&p_Pl2, g_Pl2);
    cudaGetSymbolAddress((void**)&p_Pu,  g_Pu);
    cudaGetSymbolAddress((void**)&p_Vp,  g_Vp);

    // allow >48KB dynamic smem (non-stream API; capture-safe)
    cudaFuncSetAttribute(k_l1, cudaFuncAttributeMaxDynamicSharedMemorySize, SM_BYTES);
    cudaFuncSetAttribute(k_l2, cudaFuncAttributeMaxDynamicSharedMemorySize, SM_BYTES);
    cudaFuncSetAttribute(k_u,  cudaFuncAttributeMaxDynamicSharedMemorySize, SM_BYTES);
    cudaFuncSetAttribute(k_V,  cudaFuncAttributeMaxDynamicSharedMemorySize, SM_BYTES);

    // 1) merged prep: pool-pack + label projections + weight transpose-pack
    prep_kernel<<<PREP_TOTAL, 256>>>(hs, est, een, emb, Wh1, Wt1, Wh2, Wt2, Wbil);

    // 2) L1 partials (2 nets x split-K4): 384 blocks
    k_l1<<<dim3(H1_/64, ROWS_/128, 8), 256, SM_BYTES>>>(p_Pl1);

    // 3) combine L1 -> packed h1
    combine_l1<<<(2*512*384 + 255)/256, 256>>>(bh1, bt1, elab);

    // 4) L2 partials (2 nets x split-K8): 384 blocks
    k_l2<<<dim3(H2_/64, ROWS_/128, 16), 256, SM_BYTES>>>(p_Pl2);

    // 5) combine L2 -> head/tail fp32 + packed
    combine_l2<<<(2*512*192 + 255)/256, 256>>>(bh2, bt2);

    // 6) per-entity linear terms
    lhlt_kernel<<<(ROWS_*32 + 255)/256, 256>>>(Wlin);

    // 7) u partials (split-K6): 288 blocks
    k_u<<<dim3((2*H2_)/64, ROWS_/128, 6), 256, SM_BYTES>>>(p_Pu);

    // 8) combine u -> packed U
    combine_u<<<(512*384 + 255)/256, 256>>>();

    // 9) V partials (4 bo x split-K4): 128 blocks
    k_V<<<dim3(E_/64, E_/128, 16), 256, SM_BYTES>>>(p_Vp);

    // 10) per-pair lookup + linear terms + bias
    gather_kernel<<<(B_*P_ + 255)/256, 256>>>(hidx, tidx, blin, (float*)d_out);
}

// round 16
// speedup vs baseline: 1.0419x; 1.0419x over previous
#include <cuda_runtime.h>
#include <cuda_fp16.h>
#include <cstdint>

// Problem constants (fixed by the reference)
#define B_    2
#define T_    512
#define D_    768
#define E_    256
#define P_    65536
#define H1_   768
#define H2_   384
#define NL_   5
#define ROWS_ (B_*E_)          // 512 fused (b,e) rows

#define PL1_SLAB (ROWS_*H1_)   // 393216
#define PL2_SLAB (ROWS_*H2_)   // 196608
#define PU_SLAB  (ROWS_*2*H2_) // 393216

// ---------------- scratch (static device globals; no allocation) ------------
__device__ float g_eph[NL_*H1_];            // emb @ Wh1[768:]         [5,768]
__device__ float g_ept[NL_*H1_];            // emb @ Wt1[768:]         [5,768]
__device__ float g_Pl1[4*PL1_SLAB];         // L1 partials [net*2+kp]
__device__ float g_Pl2[8*PL2_SLAB];         // L2 partials [net*4+kp]
__device__ float g_head[ROWS_*H2_];         // head_all fp32 (lhlt)
__device__ float g_tail[ROWS_*H2_];         // tail_all fp32 (lhlt)
__device__ float g_Pu[4*PU_SLAB];           // u partials [kp]
__device__ float g_Vp[16*E_*E_];            // V partials [bo*4+kp][256*256]
__device__ float g_V[4*E_*E_];              // dense biaffine table [bo][h][t]
__device__ float g_lh[ROWS_*2];
__device__ float g_lt[ROWS_*2];

// packed hi/lo half2 planes (u32 = half2 of one k-pair), all 16B aligned
__device__ __align__(16) uint32_t g_pooledP_h[512*384], g_pooledP_l[512*384];
__device__ __align__(16) uint32_t g_W1P_h[2*768*384],  g_W1P_l[2*768*384];
__device__ __align__(16) uint32_t g_W2P_h[2*384*384],  g_W2P_l[2*384*384];
__device__ __align__(16) uint32_t g_WbilP_h[768*192],  g_WbilP_l[768*192];
__device__ __align__(16) uint32_t g_h1P_h[2*512*384],  g_h1P_l[2*512*384];
__device__ __align__(16) uint32_t g_headP_h[512*192],  g_headP_l[512*192];
__device__ __align__(16) uint32_t g_tailP_h[512*192],  g_tailP_l[512*192];
__device__ __align__(16) uint32_t g_UP_h[512*384],     g_UP_l[512*384];

// ---------------- fp16 helpers ----------------------------------------------
__device__ __forceinline__ void mma_f16(float c[4],
                                        const uint32_t a[4],
                                        const uint32_t b[2]) {
    asm volatile(
        "mma.sync.aligned.m16n8k16.row.col.f32.f16.f16.f32 "
        "{%0,%1,%2,%3}, {%4,%5,%6,%7}, {%8,%9}, {%0,%1,%2,%3};"
        : "+f"(c[0]), "+f"(c[1]), "+f"(c[2]), "+f"(c[3])
        : "r"(a[0]), "r"(a[1]), "r"(a[2]), "r"(a[3]), "r"(b[0]), "r"(b[1]));
}
__device__ __forceinline__ uint32_t pk2(__half a, __half b) {
    __half2 t = __halves2half2(a, b);
    return *reinterpret_cast<uint32_t*>(&t);
}
__device__ __forceinline__ void hsplit2(float x0, float x1,
                                        uint32_t& hi, uint32_t& lo) {
    __half h0 = __float2half_rn(x0), h1 = __float2half_rn(x1);
    float l0 = x0 - __half2float(h0);
    float l1 = x1 - __half2float(h1);
    hi = pk2(h0, h1);
    lo = pk2(__float2half_rn(l0), __float2half_rn(l1));
}

// ---------------- cp.async helpers ------------------------------------------
__device__ __forceinline__ uint32_t smem_u32(const void* p) {
    return (uint32_t)__cvta_generic_to_shared(p);
}
__device__ __forceinline__ void cp16(uint32_t dst, const void* src) {
    asm volatile("cp.async.cg.shared.global [%0], [%1], 16;"
                 :: "r"(dst), "l"(src) : "memory");
}
__device__ __forceinline__ void cp_commit() {
    asm volatile("cp.async.commit_group;" ::: "memory");
}
template<int NN> __device__ __forceinline__ void cp_wait() {
    asm volatile("cp.async.wait_group %0;" :: "n"(NN) : "memory");
}

// smem layout (validated): u32 words, stride 36 per row.
// Row: words 0..15 = hi k-pairs 0..15, 16..31 = lo.  A 128 rows, B 64 rows.
#define AW2      36
#define A_BUF_W  (128*AW2)   // 4608
#define B_BUF_W  (64*AW2)    // 2304
#define SM_WORDS (2*A_BUF_W + 2*B_BUF_W)  // 13824 words = 55296 B
#define SM_BYTES (SM_WORDS*4)

// ---------------- packed-operand GEMM core (BK=32, cp.async staging) --------
// C[bm:bm+128, bn:bn+64] = 3-term fp16-split product of packed A,B (NT).
// A planes [M][ldaW] (ldaW = total kpairs), B planes [N][ldbW].
// kpStart in kpairs (multiple of 4), nk = number of 16-kpair tiles.
__device__ __forceinline__ void gemm_core_p(
    const uint32_t* __restrict__ Ahi, const uint32_t* __restrict__ Alo, int ldaW,
    const uint32_t* __restrict__ Bhi, const uint32_t* __restrict__ Blo, int ldbW,
    float* __restrict__ C, int N, int kpStart, int nk)
{
    extern __shared__ uint32_t smw[];
    uint32_t* As = smw;                 // 2 bufs x A_BUF_W
    uint32_t* Bs = smw + 2*A_BUF_W;     // 2 bufs x B_BUF_W

    const int tid = threadIdx.x;
    const int bm = blockIdx.y * 128, bn = blockIdx.x * 64;
    const int lane = tid & 31, wid = tid >> 5;
    const int wm = wid & 3, wn = wid >> 2;     // 4 x 2 warp grid
    const int q = lane >> 2, r = lane & 3;

    // A staging: row = tid>>1, half = tid&1 (8 hi + 8 lo words each)
    const int arow = tid >> 1, ahalf = tid & 1;
    const uint32_t* gAh = Ahi + (size_t)(bm+arow)*ldaW + kpStart + ahalf*8;
    const uint32_t* gAl = Alo + (size_t)(bm+arow)*ldaW + kpStart + ahalf*8;
    const uint32_t sA = smem_u32(As) + (uint32_t)(arow*AW2 + ahalf*8)*4;

    // B staging: row = tid>>2, quarter = tid&3 (4 hi + 4 lo words each)
    const int brow = tid >> 2, bq = tid & 3;
    const uint32_t* gBh = Bhi + (size_t)(bn+brow)*ldbW + kpStart + bq*4;
    const uint32_t* gBl = Blo + (size_t)(bn+brow)*ldbW + kpStart + bq*4;
    const uint32_t sB = smem_u32(Bs) + (uint32_t)(brow*AW2 + bq*4)*4;

    auto issue = [&](int t, int buf) {
        uint32_t a = sA + (uint32_t)buf*(A_BUF_W*4);
        const uint32_t* sh = gAh + t*16;
        const uint32_t* sl = gAl + t*16;
        cp16(a,      sh);     cp16(a + 16, sh + 4);
        cp16(a + 64, sl);     cp16(a + 80, sl + 4);
        uint32_t b = sB + (uint32_t)buf*(B_BUF_W*4);
        cp16(b,      gBh + t*16);
        cp16(b + 64, gBl + t*16);
        cp_commit();
    };

    float acc[2][4][4];
    #pragma unroll
    for (int f = 0; f < 2; f++)
        #pragma unroll
        for (int g = 0; g < 4; g++)
            #pragma unroll
            for (int i = 0; i < 4; i++) acc[f][g][i] = 0.f;

    issue(0, 0);
    if (nk > 1) issue(1, 1);

    for (int t = 0; t < nk; t++) {
        int cur = t & 1;
        if (t + 1 < nk) cp_wait<1>(); else cp_wait<0>();
        __syncthreads();

        // ---- compute tile t from buffer cur (validated core) ----
        #pragma unroll
        for (int s = 0; s < 2; s++) {
            uint32_t ah[2][4], al[2][4];
            #pragma unroll
            for (int f = 0; f < 2; f++) {
                int m0 = wm*32 + f*16 + q;
                int w0 = cur*A_BUF_W + m0*AW2 + s*8 + r;
                int w1 = cur*A_BUF_W + (m0+8)*AW2 + s*8 + r;
                ah[f][0] = As[w0];      ah[f][1] = As[w1];
                ah[f][2] = As[w0+4];    ah[f][3] = As[w1+4];
                al[f][0] = As[w0+16];   al[f][1] = As[w1+16];
                al[f][2] = As[w0+20];   al[f][3] = As[w1+20];
            }
            #pragma unroll
            for (int g = 0; g < 4; g++) {
                int nn = wn*32 + g*8 + q;
                int wb = cur*B_BUF_W + nn*AW2 + s*8 + r;
                uint32_t bh[2] = {Bs[wb],    Bs[wb+4]};
                uint32_t bl[2] = {Bs[wb+16], Bs[wb+20]};
                #pragma unroll
                for (int f = 0; f < 2; f++) {
                    mma_f16(acc[f][g], ah[f], bh);
                    mma_f16(acc[f][g], ah[f], bl);
                    mma_f16(acc[f][g], al[f], bh);
                }
            }
        }
        __syncthreads();                       // all reads of buf cur done
        if (t + 2 < nk) issue(t + 2, cur);     // refill cur for tile t+2
    }

    // epilogue: m16n8 frag: c0 (q,2r), c1 (q,2r+1), c2 (q+8,2r), c3 (q+8,2r+1)
    #pragma unroll
    for (int f = 0; f < 2; f++) {
        int row0 = bm + wm*32 + f*16 + q;
        #pragma unroll
        for (int g = 0; g < 4; g++) {
            int ncol = bn + wn*32 + g*8 + r*2;
            *(float2*)(C + (size_t)row0*N + ncol) =
                make_float2(acc[f][g][0], acc[f][g][1]);
            *(float2*)(C + (size_t)(row0+8)*N + ncol) =
                make_float2(acc[f][g][2], acc[f][g][3]);
        }
    }
}

// ---------------- GEMM wrappers (R14-validated split config) -----------------
// L1: Pl1[net*2+kp] = pooled @ W1[net] slice   grid(12,4,4) = 192
__global__ __launch_bounds__(256, 3) void k_l1(float* __restrict__ Pl1)
{
    int z = blockIdx.z, net = z >> 1, kp = z & 1;
    gemm_core_p(g_pooledP_h, g_pooledP_l, 384,
                g_W1P_h + (size_t)net*768*384, g_W1P_l + (size_t)net*768*384, 384,
                Pl1 + (size_t)z*PL1_SLAB, H1_, kp*192, 12);
}

// L2: Pl2[net*4+kp] = h1[net] @ W2[net]   grid(6,4,8) = 192
__global__ __launch_bounds__(256, 3) void k_l2(float* __restrict__ Pl2)
{
    int z = blockIdx.z, net = z >> 2, kp = z & 3;
    gemm_core_p(g_h1P_h + (size_t)net*512*384, g_h1P_l + (size_t)net*512*384, 384,
                g_W2P_h + (size_t)net*384*384, g_W2P_l + (size_t)net*384*384, 384,
                Pl2 + (size_t)z*PL2_SLAB, H2_, kp*96, 6);
}

// u: Pu[kp] = head @ W_bil   grid(12,4,4) = 192
__global__ __launch_bounds__(256, 3) void k_u(float* __restrict__ Pu)
{
    int kp = blockIdx.z;
    gemm_core_p(g_headP_h, g_headP_l, 192,
                g_WbilP_h, g_WbilP_l, 192,
                Pu + (size_t)kp*PU_SLAB, 2*H2_, kp*48, 3);
}

// V: Vp[bo*4+kp] = U[b,:,o-slice] @ tail_b^T   grid(4,2,16) = 128
__global__ __launch_bounds__(256, 3) void k_V(float* __restrict__ Vp)
{
    int z = blockIdx.z, bo = z >> 2, kp = z & 3;
    int b = bo >> 1, o = bo & 1;
    gemm_core_p(g_UP_h + (size_t)(b*E_)*384 + o*192,
                g_UP_l + (size_t)(b*E_)*384 + o*192, 384,
                g_tailP_h + (size_t)(b*E_)*192,
                g_tailP_l + (size_t)(b*E_)*192, 192,
                Vp + (size_t)z*E_*E_, E_, kp*48, 3);
}

// ---------------- merged prep: pool-pack + labelproj + weight-pack -----------
#define PREP_POOL   512
#define PREP_LPROJ  (PREP_POOL + 30)
#define PREP_TOTAL  (PREP_LPROJ + 1008)

__global__ void prep_kernel(const float* __restrict__ hs,
                            const int* __restrict__ st,
                            const int* __restrict__ en,
                            const float* __restrict__ emb,
                            const float* __restrict__ Wh1,
                            const float* __restrict__ Wt1,
                            const float* __restrict__ Wh2,
                            const float* __restrict__ Wt2,
                            const float* __restrict__ Wbil) {
    __shared__ float sbuf[64][33];
    int bz = blockIdx.x;
    int tid = threadIdx.x;

    if (bz < PREP_POOL) {
        int be = bz;
        int b  = be >> 8;
        int s  = st[be];
        int len = en[be] - s;
        int cl  = len < 1 ? 1 : len;
        float inv = 1.0f / (float)cl;
        const float* base = hs + ((size_t)(b*T_ + s))*D_;
        for (int dp = tid; dp < D_/2; dp += blockDim.x) {
            int d = 2*dp;
            float a0 = 0.f, a1 = 0.f;
            for (int t = 0; t < len; t++) {
                a0 += base[(size_t)t*D_ + d];
                a1 += base[(size_t)t*D_ + d + 1];
            }
            uint32_t hi, lo;
            hsplit2(a0*inv, a1*inv, hi, lo);
            g_pooledP_h[(size_t)be*384 + dp] = hi;
            g_pooledP_l[(size_t)be*384 + dp] = lo;
        }
        return;
    }
    if (bz < PREP_LPROJ) {
        int gid = (bz - PREP_POOL)*256 + tid;      // < 7680 = 2*NL*H1
        int half = gid / (NL_*H1_);
        int rr   = gid - half*(NL_*H1_);
        int l = rr / H1_, n = rr - l*H1_;
        const float* W1 = half ? Wt1 : Wh1;
        const float* wp = W1 + (size_t)D_*H1_ + n;
        const float* ep = emb + (size_t)l*D_;
        float acc = 0.f;
        #pragma unroll 4
        for (int k = 0; k < D_; k++) acc += ep[k] * wp[(size_t)k*H1_];
        if (half) g_ept[rr] = acc; else g_eph[rr] = acc;
        return;
    }

    int job = bz - PREP_LPROJ;
    const float* src; int K, N; uint32_t *dh, *dl; int local;
    if (job < 288)      { src = Wh1;            K=768; N=768; dh=g_W1P_h;             dl=g_W1P_l;             local=job; }
    else if (job < 576) { src = Wt1;            K=768; N=768; dh=g_W1P_h+768*384;     dl=g_W1P_l+768*384;     local=job-288; }
    else if (job < 720) { src = Wh2;            K=768; N=384; dh=g_W2P_h;             dl=g_W2P_l;             local=job-576; }
    else if (job < 864) { src = Wt2;            K=768; N=384; dh=g_W2P_h+384*384;     dl=g_W2P_l+384*384;     local=job-720; }
    else if (job < 936) { src = Wbil;           K=384; N=384; dh=g_WbilP_h;           dl=g_WbilP_l;           local=job-864; }
    else                { src = Wbil+384*384;   K=384; N=384; dh=g_WbilP_h+384*192;   dl=g_WbilP_l+384*192;   local=job-936; }
    int ntiles = N >> 5;
    int kt = local / ntiles, nt = local - kt*ntiles;

    for (int i = tid; i < 64*32; i += 256) {
        int kk = i >> 5, n = i & 31;
        sbuf[kk][n] = src[(size_t)(kt*64 + kk)*N + nt*32 + n];
    }
    __syncthreads();
    int ldW = K >> 1;
    for (int i = tid; i < 32*32; i += 256) {
        int n = i >> 5, p = i & 31;
        uint32_t hi, lo;
        hsplit2(sbuf[2*p][n], sbuf[2*p+1][n], hi, lo);
        size_t off = (size_t)(nt*32 + n)*ldW + kt*32 + p;
        dh[off] = hi;
        dl[off] = lo;
    }
}

// ---------------- combine L1: h1P = pack(relu(sum2 Pl1 + b1 + lbias)) -------
__global__ void combine_l1(const float* __restrict__ bh1,
                           const float* __restrict__ bt1,
                           const int* __restrict__ labels) {
    int gid = blockIdx.x*blockDim.x + threadIdx.x;   // 2*512*384
    if (gid >= 2*512*384) return;
    int net = gid / (512*384);
    int rr  = gid - net*(512*384);
    int row = rr / 384, wp = rr - row*384;
    int col = 2*wp;
    const float* base0 = g_Pl1 + (size_t)(net*2  )*PL1_SLAB + (size_t)row*H1_ + col;
    const float* base1 = g_Pl1 + (size_t)(net*2+1)*PL1_SLAB + (size_t)row*H1_ + col;
    const float* bs = net ? bt1 : bh1;
    const float* lb = (net ? g_ept : g_eph) + (size_t)labels[row]*H1_ + col;
    float v0 = fmaxf(base0[0] + base1[0] + bs[col]   + lb[0], 0.f);
    float v1 = fmaxf(base0[1] + base1[1] + bs[col+1] + lb[1], 0.f);
    uint32_t hi, lo;
    hsplit2(v0, v1, hi, lo);
    g_h1P_h[(size_t)net*512*384 + rr] = hi;
    g_h1P_l[(size_t)net*512*384 + rr] = lo;
}

// ---------------- combine L2: head/tail fp32 + packed ------------------------
__global__ void combine_l2(const float* __restrict__ bh2,
                           const float* __restrict__ bt2) {
    int gid = blockIdx.x*blockDim.x + threadIdx.x;   // 2*512*192
    if (gid >= 2*512*192) return;
    int net = gid / (512*192);
    int rr  = gid - net*(512*192);
    int row = rr / 192, wp = rr - row*192;
    int col = 2*wp;
    const float* bs = net ? bt2 : bh2;
    float v0 = bs[col], v1 = bs[col+1];
    #pragma unroll
    for (int kp = 0; kp < 4; kp++) {
        const float* p = g_Pl2 + (size_t)(net*4+kp)*PL2_SLAB + (size_t)row*H2_ + col;
        v0 += p[0]; v1 += p[1];
    }
    v0 = fmaxf(v0, 0.f); v1 = fmaxf(v1, 0.f);
    uint32_t hi, lo;
    hsplit2(v0, v1, hi, lo);
    if (net) {
        g_tail[(size_t)row*H2_ + col] = v0;
        g_tail[(size_t)row*H2_ + col + 1] = v1;
        g_tailP_h[rr] = hi; g_tailP_l[rr] = lo;
    } else {
        g_head[(size_t)row*H2_ + col] = v0;
        g_head[(size_t)row*H2_ + col + 1] = v1;
        g_headP_h[rr] = hi; g_headP_l[rr] = lo;
    }
}

// ---------------- combine u: UP = pack(sum4 Pu) ------------------------------
__global__ void combine_u() {
    int gid = blockIdx.x*blockDim.x + threadIdx.x;   // 512*384
    if (gid >= 512*384) return;
    int row = gid / 384, wp = gid - row*384;
    int col = 2*wp;
    float v0 = 0.f, v1 = 0.f;
    #pragma unroll
    for (int kp = 0; kp < 4; kp++) {
        const float* p = g_Pu + (size_t)kp*PU_SLAB + (size_t)row*(2*H2_) + col;
        v0 += p[0]; v1 += p[1];
    }
    uint32_t hi, lo;
    hsplit2(v0, v1, hi, lo);
    g_UP_h[gid] = hi;
    g_UP_l[gid] = lo;
}

// ---------------- merged: combine_V (dense table) + lhlt ---------------------
// blocks 0..255: combine_V (65536 float4 groups); blocks 256..319: lhlt.
__global__ void combine_V_lhlt(const float* __restrict__ Wlin) {
    int bz = blockIdx.x;
    int tid = threadIdx.x;
    if (bz < 256) {
        int idx = bz*256 + tid;              // 65536 float4 groups
        const int per = E_*E_/4;             // 16384 per bo
        int bo = idx / per, rr = idx - bo*per;
        float4 v = make_float4(0.f, 0.f, 0.f, 0.f);
        #pragma unroll
        for (int kp = 0; kp < 4; kp++) {
            float4 a = ((const float4*)(g_Vp + (size_t)(bo*4+kp)*E_*E_))[rr];
            v.x += a.x; v.y += a.y; v.z += a.z; v.w += a.w;
        }
        ((float4*)g_V)[idx] = v;
        return;
    }
    // lhlt: 64 blocks x 256 threads = 16384 = 512 warps
    int gid  = (bz - 256)*256 + tid;
    int w    = gid >> 5;
    int lane = gid & 31;
    if (w >= ROWS_) return;
    float s0=0.f, s1=0.f, s2=0.f, s3=0.f;
    for (int j = lane; j < H2_; j += 32) {
        float hv = g_head[(size_t)w*H2_ + j];
        float tv = g_tail[(size_t)w*H2_ + j];
        s0 += hv * Wlin[j*2+0];
        s1 += hv * Wlin[j*2+1];
        s2 += tv * Wlin[(H2_+j)*2+0];
        s3 += tv * Wlin[(H2_+j)*2+1];
    }
    #pragma unroll
    for (int off = 16; off > 0; off >>= 1) {
        s0 += __shfl_down_sync(0xffffffffu, s0, off);
        s1 += __shfl_down_sync(0xffffffffu, s1, off);
        s2 += __shfl_down_sync(0xffffffffu, s2, off);
        s3 += __shfl_down_sync(0xffffffffu, s3, off);
    }
    if (lane == 0) {
        g_lh[w*2+0] = s0; g_lh[w*2+1] = s1;
        g_lt[w*2+0] = s2; g_lt[w*2+1] = s3;
    }
}

// ---------------- final per-pair lookup (dense V) ----------------------------
__global__ void gather_kernel(const int* __restrict__ hidx,
                              const int* __restrict__ tidx,
                              const float* __restrict__ blin,
                              float* __restrict__ out) {
    int gid = blockIdx.x*blockDim.x + threadIdx.x;   // B*P = 131072
    if (gid >= B_*P_) return;
    int b = gid >> 16;
    int h = hidx[gid];
    int t = tidx[gid];
    int rh = (b << 8) + h;
    int rt = (b << 8) + t;
    size_t off = (size_t)(h << 8) + t;
    float v0 = g_V[((size_t)(b*2+0) << 16) + off];
    float v1 = g_V[((size_t)(b*2+1) << 16) + off];
    float2 r;
    r.x = v0 + g_lh[rh*2+0] + g_lt[rt*2+0] + blin[0];
    r.y = v1 + g_lh[rh*2+1] + g_lt[rt*2+1] + blin[1];
    ((float2*)out)[gid] = r;
}

// ---------------- launch ----------------------------------------------------
extern "C" void kernel_launch(void* const* d_in, const int* in_sizes, int n_in,
                              void* d_out, int out_size) {
    const float* hs   = (const float*)d_in[0];
    const float* emb  = (const float*)d_in[1];
    const float* Wh1  = (const float*)d_in[2];
    const float* bh1  = (const float*)d_in[3];
    const float* Wh2  = (const float*)d_in[4];
    const float* bh2  = (const float*)d_in[5];
    const float* Wt1  = (const float*)d_in[6];
    const float* bt1  = (const float*)d_in[7];
    const float* Wt2  = (const float*)d_in[8];
    const float* bt2  = (const float*)d_in[9];
    const float* Wbil = (const float*)d_in[10];
    const float* Wlin = (const float*)d_in[11];
    const float* blin = (const float*)d_in[12];
    const int*   est  = (const int*)d_in[13];
    const int*   een  = (const int*)d_in[14];
    const int*   elab = (const int*)d_in[15];
    const int*   hidx = (const int*)d_in[16];
    const int*   tidx = (const int*)d_in[17];

    float *p_Pl1, *p_Pl2, *p_Pu, *p_Vp;
    cudaGetSymbolAddress((void**)&p_Pl1, g_Pl1);
    cudaGetSymbolAddress((void**)&p_Pl2, g_Pl2);
    cudaGetSymbolAddress((void**)&p_Pu,  g_Pu);
    cudaGetSymbolAddress((void**)&p_Vp,  g_Vp);

    // allow >48KB dynamic smem (non-stream API; capture-safe)
    cudaFuncSetAttribute(k_l1, cudaFuncAttributeMaxDynamicSharedMemorySize, SM_BYTES);
    cudaFuncSetAttribute(k_l2, cudaFuncAttributeMaxDynamicSharedMemorySize, SM_BYTES);
    cudaFuncSetAttribute(k_u,  cudaFuncAttributeMaxDynamicSharedMemorySize, SM_BYTES);
    cudaFuncSetAttribute(k_V,  cudaFuncAttributeMaxDynamicSharedMemorySize, SM_BYTES);

    // 1) merged prep: pool-pack + label projections + weight transpose-pack
    prep_kernel<<<PREP_TOTAL, 256>>>(hs, est, een, emb, Wh1, Wt1, Wh2, Wt2, Wbil);

    // 2) L1 partials (2 nets x split-K2): 192 blocks
    k_l1<<<dim3(H1_/64, ROWS_/128, 4), 256, SM_BYTES>>>(p_Pl1);

    // 3) combine L1 -> packed h1
    combine_l1<<<(2*512*384 + 255)/256, 256>>>(bh1, bt1, elab);

    // 4) L2 partials (2 nets x split-K4): 192 blocks
    k_l2<<<dim3(H2_/64, ROWS_/128, 8), 256, SM_BYTES>>>(p_Pl2);

    // 5) combine L2 -> head/tail fp32 + packed
    combine_l2<<<(2*512*192 + 255)/256, 256>>>(bh2, bt2);

    // 6) u partials (split-K4): 192 blocks
    k_u<<<dim3((2*H2_)/64, ROWS_/128, 4), 256, SM_BYTES>>>(p_Pu);

    // 7) combine u -> packed U
    combine_u<<<(512*384 + 255)/256, 256>>>();

    // 8) V partials (4 bo x split-K4): 128 blocks
    k_V<<<dim3(E_/64, E_/128, 16), 256, SM_BYTES>>>(p_Vp);

    // 9) merged: densify V + per-entity linear terms
    combine_V_lhlt<<<320, 256>>>(Wlin);

    // 10) per-pair lookup + linear terms + bias
    gather_kernel<<<(B_*P_ + 255)/256, 256>>>(hidx, tidx, blin, (float*)d_out);
}

// round 17
// speedup vs baseline: 1.2082x; 1.1596x over previous
#include <cuda_runtime.h>
#include <cuda_fp16.h>
#include <cstdint>

// Problem constants (fixed by the reference)
#define B_    2
#define T_    512
#define D_    768
#define E_    256
#define P_    65536
#define H1_   768
#define H2_   384
#define NL_   5
#define ROWS_ (B_*E_)          // 512 fused (b,e) rows

#define PL1_SLAB (ROWS_*H1_)   // 393216
#define PL2_SLAB (ROWS_*H2_)   // 196608
#define PU_SLAB  (ROWS_*2*H2_) // 393216

// ---------------- scratch (static device globals; no allocation) ------------
__device__ float g_eph[NL_*H1_];            // emb @ Wh1[768:]         [5,768]
__device__ float g_ept[NL_*H1_];            // emb @ Wt1[768:]         [5,768]
__device__ float g_Pl1[4*PL1_SLAB];         // L1 partials [net*2+kp]
__device__ float g_Pl2[8*PL2_SLAB];         // L2 partials [net*4+kp]
__device__ float g_head[ROWS_*H2_];         // head_all fp32 (lhlt)
__device__ float g_tail[ROWS_*H2_];         // tail_all fp32 (lhlt)
__device__ float g_Pu[4*PU_SLAB];           // u partials [kp]
__device__ float g_Vp[16*E_*E_];            // V partials [bo*4+kp][256*256]
__device__ float g_lh[ROWS_*2];
__device__ float g_lt[ROWS_*2];

// packed hi/lo half2 planes (u32 = half2 of one k-pair), all 16B aligned
__device__ __align__(16) uint32_t g_pooledP_h[512*384], g_pooledP_l[512*384];
__device__ __align__(16) uint32_t g_W1P_h[2*768*384],  g_W1P_l[2*768*384];
__device__ __align__(16) uint32_t g_W2P_h[2*384*384],  g_W2P_l[2*384*384];
__device__ __align__(16) uint32_t g_WbilP_h[768*192],  g_WbilP_l[768*192];
__device__ __align__(16) uint32_t g_h1P_h[2*512*384],  g_h1P_l[2*512*384];
__device__ __align__(16) uint32_t g_headP_h[512*192],  g_headP_l[512*192];
__device__ __align__(16) uint32_t g_tailP_h[512*192],  g_tailP_l[512*192];
__device__ __align__(16) uint32_t g_UP_h[512*384],     g_UP_l[512*384];

// ---------------- fp16 helpers ----------------------------------------------
__device__ __forceinline__ void mma_f16(float c[4],
                                        const uint32_t a[4],
                                        const uint32_t b[2]) {
    asm volatile(
        "mma.sync.aligned.m16n8k16.row.col.f32.f16.f16.f32 "
        "{%0,%1,%2,%3}, {%4,%5,%6,%7}, {%8,%9}, {%0,%1,%2,%3};"
        : "+f"(c[0]), "+f"(c[1]), "+f"(c[2]), "+f"(c[3])
        : "r"(a[0]), "r"(a[1]), "r"(a[2]), "r"(a[3]), "r"(b[0]), "r"(b[1]));
}
__device__ __forceinline__ uint32_t pk2(__half a, __half b) {
    __half2 t = __halves2half2(a, b);
    return *reinterpret_cast<uint32_t*>(&t);
}
__device__ __forceinline__ void hsplit2(float x0, float x1,
                                        uint32_t& hi, uint32_t& lo) {
    __half h0 = __float2half_rn(x0), h1 = __float2half_rn(x1);
    float l0 = x0 - __half2float(h0);
    float l1 = x1 - __half2float(h1);
    hi = pk2(h0, h1);
    lo = pk2(__float2half_rn(l0), __float2half_rn(l1));
}

// ---------------- cp.async helpers ------------------------------------------
__device__ __forceinline__ uint32_t smem_u32(const void* p) {
    return (uint32_t)__cvta_generic_to_shared(p);
}
__device__ __forceinline__ void cp16(uint32_t dst, const void* src) {
    asm volatile("cp.async.cg.shared.global [%0], [%1], 16;"
                 :: "r"(dst), "l"(src) : "memory");
}
__device__ __forceinline__ void cp_commit() {
    asm volatile("cp.async.commit_group;" ::: "memory");
}
template<int NN> __device__ __forceinline__ void cp_wait() {
    asm volatile("cp.async.wait_group %0;" :: "n"(NN) : "memory");
}

// smem layout (validated): u32 words, stride 36 per row.
// Row: words 0..15 = hi k-pairs 0..15, 16..31 = lo.  A 128 rows, B 64 rows.
#define AW2      36
#define A_BUF_W  (128*AW2)   // 4608
#define B_BUF_W  (64*AW2)    // 2304
#define SM_WORDS (2*A_BUF_W + 2*B_BUF_W)  // 13824 words = 55296 B
#define SM_BYTES (SM_WORDS*4)

// ---------------- packed-operand GEMM core (BK=32, cp.async staging) --------
// C[bm:bm+128, bn:bn+64] = 3-term fp16-split product of packed A,B (NT).
// A planes [M][ldaW] (ldaW = total kpairs), B planes [N][ldbW].
// kpStart in kpairs (multiple of 4), nk = number of 16-kpair tiles.
__device__ __forceinline__ void gemm_core_p(
    const uint32_t* __restrict__ Ahi, const uint32_t* __restrict__ Alo, int ldaW,
    const uint32_t* __restrict__ Bhi, const uint32_t* __restrict__ Blo, int ldbW,
    float* __restrict__ C, int N, int kpStart, int nk)
{
    extern __shared__ uint32_t smw[];
    uint32_t* As = smw;                 // 2 bufs x A_BUF_W
    uint32_t* Bs = smw + 2*A_BUF_W;     // 2 bufs x B_BUF_W

    const int tid = threadIdx.x;
    const int bm = blockIdx.y * 128, bn = blockIdx.x * 64;
    const int lane = tid & 31, wid = tid >> 5;
    const int wm = wid & 3, wn = wid >> 2;     // 4 x 2 warp grid
    const int q = lane >> 2, r = lane & 3;

    // A staging: row = tid>>1, half = tid&1 (8 hi + 8 lo words each)
    const int arow = tid >> 1, ahalf = tid & 1;
    const uint32_t* gAh = Ahi + (size_t)(bm+arow)*ldaW + kpStart + ahalf*8;
    const uint32_t* gAl = Alo + (size_t)(bm+arow)*ldaW + kpStart + ahalf*8;
    const uint32_t sA = smem_u32(As) + (uint32_t)(arow*AW2 + ahalf*8)*4;

    // B staging: row = tid>>2, quarter = tid&3 (4 hi + 4 lo words each)
    const int brow = tid >> 2, bq = tid & 3;
    const uint32_t* gBh = Bhi + (size_t)(bn+brow)*ldbW + kpStart + bq*4;
    const uint32_t* gBl = Blo + (size_t)(bn+brow)*ldbW + kpStart + bq*4;
    const uint32_t sB = smem_u32(Bs) + (uint32_t)(brow*AW2 + bq*4)*4;

    auto issue = [&](int t, int buf) {
        uint32_t a = sA + (uint32_t)buf*(A_BUF_W*4);
        const uint32_t* sh = gAh + t*16;
        const uint32_t* sl = gAl + t*16;
        cp16(a,      sh);     cp16(a + 16, sh + 4);
        cp16(a + 64, sl);     cp16(a + 80, sl + 4);
        uint32_t b = sB + (uint32_t)buf*(B_BUF_W*4);
        cp16(b,      gBh + t*16);
        cp16(b + 64, gBl + t*16);
        cp_commit();
    };

    float acc[2][4][4];
    #pragma unroll
    for (int f = 0; f < 2; f++)
        #pragma unroll
        for (int g = 0; g < 4; g++)
            #pragma unroll
            for (int i = 0; i < 4; i++) acc[f][g][i] = 0.f;

    issue(0, 0);
    if (nk > 1) issue(1, 1);

    for (int t = 0; t < nk; t++) {
        int cur = t & 1;
        if (t + 1 < nk) cp_wait<1>(); else cp_wait<0>();
        __syncthreads();

        // ---- compute tile t from buffer cur (validated core) ----
        #pragma unroll
        for (int s = 0; s < 2; s++) {
            uint32_t ah[2][4], al[2][4];
            #pragma unroll
            for (int f = 0; f < 2; f++) {
                int m0 = wm*32 + f*16 + q;
                int w0 = cur*A_BUF_W + m0*AW2 + s*8 + r;
                int w1 = cur*A_BUF_W + (m0+8)*AW2 + s*8 + r;
                ah[f][0] = As[w0];      ah[f][1] = As[w1];
                ah[f][2] = As[w0+4];    ah[f][3] = As[w1+4];
                al[f][0] = As[w0+16];   al[f][1] = As[w1+16];
                al[f][2] = As[w0+20];   al[f][3] = As[w1+20];
            }
            #pragma unroll
            for (int g = 0; g < 4; g++) {
                int nn = wn*32 + g*8 + q;
                int wb = cur*B_BUF_W + nn*AW2 + s*8 + r;
                uint32_t bh[2] = {Bs[wb],    Bs[wb+4]};
                uint32_t bl[2] = {Bs[wb+16], Bs[wb+20]};
                #pragma unroll
                for (int f = 0; f < 2; f++) {
                    mma_f16(acc[f][g], ah[f], bh);
                    mma_f16(acc[f][g], ah[f], bl);
                    mma_f16(acc[f][g], al[f], bh);
                }
            }
        }
        __syncthreads();                       // all reads of buf cur done
        if (t + 2 < nk) issue(t + 2, cur);     // refill cur for tile t+2
    }

    // epilogue: m16n8 frag: c0 (q,2r), c1 (q,2r+1), c2 (q+8,2r), c3 (q+8,2r+1)
    #pragma unroll
    for (int f = 0; f < 2; f++) {
        int row0 = bm + wm*32 + f*16 + q;
        #pragma unroll
        for (int g = 0; g < 4; g++) {
            int ncol = bn + wn*32 + g*8 + r*2;
            *(float2*)(C + (size_t)row0*N + ncol) =
                make_float2(acc[f][g][0], acc[f][g][1]);
            *(float2*)(C + (size_t)(row0+8)*N + ncol) =
                make_float2(acc[f][g][2], acc[f][g][3]);
        }
    }
}

// ---------------- GEMM wrappers (R14-validated split config) -----------------
// L1: Pl1[net*2+kp] = pooled @ W1[net] slice   grid(12,4,4) = 192
__global__ __launch_bounds__(256, 3) void k_l1(float* __restrict__ Pl1)
{
    int z = blockIdx.z, net = z >> 1, kp = z & 1;
    gemm_core_p(g_pooledP_h, g_pooledP_l, 384,
                g_W1P_h + (size_t)net*768*384, g_W1P_l + (size_t)net*768*384, 384,
                Pl1 + (size_t)z*PL1_SLAB, H1_, kp*192, 12);
}

// L2: Pl2[net*4+kp] = h1[net] @ W2[net]   grid(6,4,8) = 192
__global__ __launch_bounds__(256, 3) void k_l2(float* __restrict__ Pl2)
{
    int z = blockIdx.z, net = z >> 2, kp = z & 3;
    gemm_core_p(g_h1P_h + (size_t)net*512*384, g_h1P_l + (size_t)net*512*384, 384,
                g_W2P_h + (size_t)net*384*384, g_W2P_l + (size_t)net*384*384, 384,
                Pl2 + (size_t)z*PL2_SLAB, H2_, kp*96, 6);
}

// u: Pu[kp] = head @ W_bil   grid(12,4,4) = 192
__global__ __launch_bounds__(256, 3) void k_u(float* __restrict__ Pu)
{
    int kp = blockIdx.z;
    gemm_core_p(g_headP_h, g_headP_l, 192,
                g_WbilP_h, g_WbilP_l, 192,
                Pu + (size_t)kp*PU_SLAB, 2*H2_, kp*48, 3);
}

// V: Vp[bo*4+kp] = U[b,:,o-slice] @ tail_b^T   grid(4,2,16) = 128
__global__ __launch_bounds__(256, 3) void k_V(float* __restrict__ Vp)
{
    int z = blockIdx.z, bo = z >> 2, kp = z & 3;
    int b = bo >> 1, o = bo & 1;
    gemm_core_p(g_UP_h + (size_t)(b*E_)*384 + o*192,
                g_UP_l + (size_t)(b*E_)*384 + o*192, 384,
                g_tailP_h + (size_t)(b*E_)*192,
                g_tailP_l + (size_t)(b*E_)*192, 192,
                Vp + (size_t)z*E_*E_, E_, kp*48, 3);
}

// ---------------- merged prep: pool-pack + labelproj + weight-pack -----------
#define PREP_POOL   512
#define PREP_LPROJ  (PREP_POOL + 30)
#define PREP_TOTAL  (PREP_LPROJ + 1008)

__global__ void prep_kernel(const float* __restrict__ hs,
                            const int* __restrict__ st,
                            const int* __restrict__ en,
                            const float* __restrict__ emb,
                            const float* __restrict__ Wh1,
                            const float* __restrict__ Wt1,
                            const float* __restrict__ Wh2,
                            const float* __restrict__ Wt2,
                            const float* __restrict__ Wbil) {
    __shared__ float sbuf[64][33];
    int bz = blockIdx.x;
    int tid = threadIdx.x;

    if (bz < PREP_POOL) {
        int be = bz;
        int b  = be >> 8;
        int s  = st[be];
        int len = en[be] - s;
        int cl  = len < 1 ? 1 : len;
        float inv = 1.0f / (float)cl;
        const float* base = hs + ((size_t)(b*T_ + s))*D_;
        for (int dp = tid; dp < D_/2; dp += blockDim.x) {
            int d = 2*dp;
            float a0 = 0.f, a1 = 0.f;
            for (int t = 0; t < len; t++) {
                a0 += base[(size_t)t*D_ + d];
                a1 += base[(size_t)t*D_ + d + 1];
            }
            uint32_t hi, lo;
            hsplit2(a0*inv, a1*inv, hi, lo);
            g_pooledP_h[(size_t)be*384 + dp] = hi;
            g_pooledP_l[(size_t)be*384 + dp] = lo;
        }
        return;
    }
    if (bz < PREP_LPROJ) {
        int gid = (bz - PREP_POOL)*256 + tid;      // < 7680 = 2*NL*H1
        int half = gid / (NL_*H1_);
        int rr   = gid - half*(NL_*H1_);
        int l = rr / H1_, n = rr - l*H1_;
        const float* W1 = half ? Wt1 : Wh1;
        const float* wp = W1 + (size_t)D_*H1_ + n;
        const float* ep = emb + (size_t)l*D_;
        float acc = 0.f;
        #pragma unroll 4
        for (int k = 0; k < D_; k++) acc += ep[k] * wp[(size_t)k*H1_];
        if (half) g_ept[rr] = acc; else g_eph[rr] = acc;
        return;
    }

    int job = bz - PREP_LPROJ;
    const float* src; int K, N; uint32_t *dh, *dl; int local;
    if (job < 288)      { src = Wh1;            K=768; N=768; dh=g_W1P_h;             dl=g_W1P_l;             local=job; }
    else if (job < 576) { src = Wt1;            K=768; N=768; dh=g_W1P_h+768*384;     dl=g_W1P_l+768*384;     local=job-288; }
    else if (job < 720) { src = Wh2;            K=768; N=384; dh=g_W2P_h;             dl=g_W2P_l;             local=job-576; }
    else if (job < 864) { src = Wt2;            K=768; N=384; dh=g_W2P_h+384*384;     dl=g_W2P_l+384*384;     local=job-720; }
    else if (job < 936) { src = Wbil;           K=384; N=384; dh=g_WbilP_h;           dl=g_WbilP_l;           local=job-864; }
    else                { src = Wbil+384*384;   K=384; N=384; dh=g_WbilP_h+384*192;   dl=g_WbilP_l+384*192;   local=job-936; }
    int ntiles = N >> 5;
    int kt = local / ntiles, nt = local - kt*ntiles;

    for (int i = tid; i < 64*32; i += 256) {
        int kk = i >> 5, n = i & 31;
        sbuf[kk][n] = src[(size_t)(kt*64 + kk)*N + nt*32 + n];
    }
    __syncthreads();
    int ldW = K >> 1;
    for (int i = tid; i < 32*32; i += 256) {
        int n = i >> 5, p = i & 31;
        uint32_t hi, lo;
        hsplit2(sbuf[2*p][n], sbuf[2*p+1][n], hi, lo);
        size_t off = (size_t)(nt*32 + n)*ldW + kt*32 + p;
        dh[off] = hi;
        dl[off] = lo;
    }
}

// ---------------- combine L1 (vectorized): h1P = pack(relu(sum2+b1+lb)) -----
// One thread: 4 cols (2 kpairs).  Threads: 2*512*192 = 196608.
__global__ void combine_l1(const float* __restrict__ bh1,
                           const float* __restrict__ bt1,
                           const int* __restrict__ labels) {
    int gid = blockIdx.x*blockDim.x + threadIdx.x;
    if (gid >= 2*512*192) return;
    int net = gid / (512*192);
    int rr  = gid - net*(512*192);
    int row = rr / 192, qq = rr - row*192;     // qq: group of 4 cols
    int col = 4*qq;
    float4 a = *(const float4*)(g_Pl1 + (size_t)(net*2  )*PL1_SLAB + (size_t)row*H1_ + col);
    float4 b = *(const float4*)(g_Pl1 + (size_t)(net*2+1)*PL1_SLAB + (size_t)row*H1_ + col);
    float4 bs = *(const float4*)((net ? bt1 : bh1) + col);
    float4 lb = *(const float4*)((net ? g_ept : g_eph) + (size_t)labels[row]*H1_ + col);
    float v0 = fmaxf(a.x + b.x + bs.x + lb.x, 0.f);
    float v1 = fmaxf(a.y + b.y + bs.y + lb.y, 0.f);
    float v2 = fmaxf(a.z + b.z + bs.z + lb.z, 0.f);
    float v3 = fmaxf(a.w + b.w + bs.w + lb.w, 0.f);
    uint32_t h0, l0, h1, l1;
    hsplit2(v0, v1, h0, l0);
    hsplit2(v2, v3, h1, l1);
    size_t wo = (size_t)net*512*384 + (size_t)row*384 + 2*qq;
    *(uint2*)(g_h1P_h + wo) = make_uint2(h0, h1);
    *(uint2*)(g_h1P_l + wo) = make_uint2(l0, l1);
}

// ---------------- combine L2 (vectorized): head/tail fp32 + packed ----------
// One thread: 4 cols (2 kpairs).  Threads: 2*512*96 = 98304.
__global__ void combine_l2(const float* __restrict__ bh2,
                           const float* __restrict__ bt2) {
    int gid = blockIdx.x*blockDim.x + threadIdx.x;
    if (gid >= 2*512*96) return;
    int net = gid / (512*96);
    int rr  = gid - net*(512*96);
    int row = rr / 96, qq = rr - row*96;
    int col = 4*qq;
    float4 bs = *(const float4*)((net ? bt2 : bh2) + col);
    float v0 = bs.x, v1 = bs.y, v2 = bs.z, v3 = bs.w;
    #pragma unroll
    for (int kp = 0; kp < 4; kp++) {
        float4 p = *(const float4*)(g_Pl2 + (size_t)(net*4+kp)*PL2_SLAB
                                          + (size_t)row*H2_ + col);
        v0 += p.x; v1 += p.y; v2 += p.z; v3 += p.w;
    }
    v0 = fmaxf(v0, 0.f); v1 = fmaxf(v1, 0.f);
    v2 = fmaxf(v2, 0.f); v3 = fmaxf(v3, 0.f);
    uint32_t h0, l0, h1, l1;
    hsplit2(v0, v1, h0, l0);
    hsplit2(v2, v3, h1, l1);
    size_t fo = (size_t)row*H2_ + col;
    size_t wo = (size_t)row*192 + 2*qq;
    if (net) {
        *(float4*)(g_tail + fo) = make_float4(v0, v1, v2, v3);
        *(uint2*)(g_tailP_h + wo) = make_uint2(h0, h1);
        *(uint2*)(g_tailP_l + wo) = make_uint2(l0, l1);
    } else {
        *(float4*)(g_head + fo) = make_float4(v0, v1, v2, v3);
        *(uint2*)(g_headP_h + wo) = make_uint2(h0, h1);
        *(uint2*)(g_headP_l + wo) = make_uint2(l0, l1);
    }
}

// ---------------- combine u (vectorized): UP = pack(sum4 Pu) -----------------
// One thread: 4 cols (2 kpairs).  Threads: 512*192 = 98304.
__global__ void combine_u() {
    int gid = blockIdx.x*blockDim.x + threadIdx.x;
    if (gid >= 512*192) return;
    int row = gid / 192, qq = gid - row*192;
    int col = 4*qq;
    float v0 = 0.f, v1 = 0.f, v2 = 0.f, v3 = 0.f;
    #pragma unroll
    for (int kp = 0; kp < 4; kp++) {
        float4 p = *(const float4*)(g_Pu + (size_t)kp*PU_SLAB
                                         + (size_t)row*(2*H2_) + col);
        v0 += p.x; v1 += p.y; v2 += p.z; v3 += p.w;
    }
    uint32_t h0, l0, h1, l1;
    hsplit2(v0, v1, h0, l0);
    hsplit2(v2, v3, h1, l1);
    size_t wo = (size_t)row*384 + 2*qq;
    *(uint2*)(g_UP_h + wo) = make_uint2(h0, h1);
    *(uint2*)(g_UP_l + wo) = make_uint2(l0, l1);
}

// ---------------- per-entity linear terms lh/lt -----------------------------
__global__ void lhlt_kernel(const float* __restrict__ Wlin) {
    int gid  = blockIdx.x*blockDim.x + threadIdx.x;
    int w    = gid >> 5;
    int lane = gid & 31;
    if (w >= ROWS_) return;
    float s0=0.f, s1=0.f, s2=0.f, s3=0.f;
    for (int j = lane; j < H2_; j += 32) {
        float hv = g_head[(size_t)w*H2_ + j];
        float tv = g_tail[(size_t)w*H2_ + j];
        s0 += hv * Wlin[j*2+0];
        s1 += hv * Wlin[j*2+1];
        s2 += tv * Wlin[(H2_+j)*2+0];
        s3 += tv * Wlin[(H2_+j)*2+1];
    }
    #pragma unroll
    for (int off = 16; off > 0; off >>= 1) {
        s0 += __shfl_down_sync(0xffffffffu, s0, off);
        s1 += __shfl_down_sync(0xffffffffu, s1, off);
        s2 += __shfl_down_sync(0xffffffffu, s2, off);
        s3 += __shfl_down_sync(0xffffffffu, s3, off);
    }
    if (lane == 0) {
        g_lh[w*2+0] = s0; g_lh[w*2+1] = s1;
        g_lt[w*2+0] = s2; g_lt[w*2+1] = s3;
    }
}

// ---------------- final per-pair lookup (sums 4 V partials per o) -----------
__global__ void gather_kernel(const int* __restrict__ hidx,
                              const int* __restrict__ tidx,
                              const float* __restrict__ blin,
                              float* __restrict__ out) {
    int gid = blockIdx.x*blockDim.x + threadIdx.x;   // B*P = 131072
    if (gid >= B_*P_) return;
    int b = gid >> 16;
    int h = hidx[gid];
    int t = tidx[gid];
    int rh = (b << 8) + h;
    int rt = (b << 8) + t;
    size_t off = (size_t)(h << 8) + t;
    float v0 = 0.f, v1 = 0.f;
    #pragma unroll
    for (int kp = 0; kp < 4; kp++) {
        v0 += g_Vp[(((size_t)(b*2+0)*4 + kp) << 16) + off];
        v1 += g_Vp[(((size_t)(b*2+1)*4 + kp) << 16) + off];
    }
    float2 r;
    r.x = v0 + g_lh[rh*2+0] + g_lt[rt*2+0] + blin[0];
    r.y = v1 + g_lh[rh*2+1] + g_lt[rt*2+1] + blin[1];
    ((float2*)out)[gid] = r;
}

// ---------------- launch ----------------------------------------------------
extern "C" void kernel_launch(void* const* d_in, const int* in_sizes, int n_in,
                              void* d_out, int out_size) {
    const float* hs   = (const float*)d_in[0];
    const float* emb  = (const float*)d_in[1];
    const float* Wh1  = (const float*)d_in[2];
    const float* bh1  = (const float*)d_in[3];
    const float* Wh2  = (const float*)d_in[4];
    const float* bh2  = (const float*)d_in[5];
    const float* Wt1  = (const float*)d_in[6];
    const float* bt1  = (const float*)d_in[7];
    const float* Wt2  = (const float*)d_in[8];
    const float* bt2  = (const float*)d_in[9];
    const float* Wbil = (const float*)d_in[10];
    const float* Wlin = (const float*)d_in[11];
    const float* blin = (const float*)d_in[12];
    const int*   est  = (const int*)d_in[13];
    const int*   een  = (const int*)d_in[14];
    const int*   elab = (const int*)d_in[15];
    const int*   hidx = (const int*)d_in[16];
    const int*   tidx = (const int*)d_in[17];

    float *p_Pl1, *p_Pl2, *p_Pu, *p_Vp;
    cudaGetSymbolAddress((void**)&p_Pl1, g_Pl1);
    cudaGetSymbolAddress((void**)&p_Pl2, g_Pl2);
    cudaGetSymbolAddress((void**)&p_Pu,  g_Pu);
    cudaGetSymbolAddress((void**)&p_Vp,  g_Vp);

    // allow >48KB dynamic smem (non-stream API; capture-safe)
    cudaFuncSetAttribute(k_l1, cudaFuncAttributeMaxDynamicSharedMemorySize, SM_BYTES);
    cudaFuncSetAttribute(k_l2, cudaFuncAttributeMaxDynamicSharedMemorySize, SM_BYTES);
    cudaFuncSetAttribute(k_u,  cudaFuncAttributeMaxDynamicSharedMemorySize, SM_BYTES);
    cudaFuncSetAttribute(k_V,  cudaFuncAttributeMaxDynamicSharedMemorySize, SM_BYTES);

    // 1) merged prep: pool-pack + label projections + weight transpose-pack
    prep_kernel<<<PREP_TOTAL, 256>>>(hs, est, een, emb, Wh1, Wt1, Wh2, Wt2, Wbil);

    // 2) L1 partials (2 nets x split-K2): 192 blocks
    k_l1<<<dim3(H1_/64, ROWS_/128, 4), 256, SM_BYTES>>>(p_Pl1);

    // 3) combine L1 -> packed h1 (vectorized)
    combine_l1<<<(2*512*192 + 255)/256, 256>>>(bh1, bt1, elab);

    // 4) L2 partials (2 nets x split-K4): 192 blocks
    k_l2<<<dim3(H2_/64, ROWS_/128, 8), 256, SM_BYTES>>>(p_Pl2);

    // 5) combine L2 -> head/tail fp32 + packed (vectorized)
    combine_l2<<<(2*512*96 + 255)/256, 256>>>(bh2, bt2);

    // 6) per-entity linear terms
    lhlt_kernel<<<(ROWS_*32 + 255)/256, 256>>>(Wlin);

    // 7) u partials (split-K4): 192 blocks
    k_u<<<dim3((2*H2_)/64, ROWS_/128, 4), 256, SM_BYTES>>>(p_Pu);

    // 8) combine u -> packed U (vectorized)
    combine_u<<<(512*192 + 255)/256, 256>>>();

    // 9) V partials (4 bo x split-K4): 128 blocks
    k_V<<<dim3(E_/64, E_/128, 16), 256, SM_BYTES>>>(p_Vp);

    // 10) per-pair lookup (sums 4 V partials) + linear terms + bias
    gather_kernel<<<(B_*P_ + 255)/256, 256>>>(hidx, tidx, blin, (float*)d_out);
}